// round 13
// baseline (speedup 1.0000x reference)
#include <cuda_runtime.h>
#include <cuda_fp16.h>
#include <cstdint>
#include <math.h>

#define H      1024
#define E      16
#define T      8192
#define TOPK   6
#define EPSV   1e-10f

// ---- main GEMM: BM=128, BN=128, BK=32; 128 thr, 4 warps (2x2), warptile 64x64
//      WARP-PRIVATE staging: no __syncthreads in mainloop.
#define BM 128
#define BN 128
#define BK 32
#define NCHUNK (H/BK)           // 32
#define STAGES 3
#define WSTG 8192               // per-warp per-stage: A 4KB + B 4KB
#define WREG (STAGES*WSTG)      // 24576 per warp
#define DSMEM (4*WREG + 256)    // 98560

// ---- router mini-GEMM (hi/lo split) + fused topk (unchanged) ----
#define LSTG   32768
#define LBOFF  (3*LSTG)
#define LTOPK  (LBOFF + 2*32768)
#define LDSMEM (LTOPK + 128*17*4 + 256)

// ---- device globals ----
__device__ int    d_counts[E];
__device__ int    d_perm_token[E*T];
__device__ int    d_perm_dest [E*T];
__device__ float  d_perm_coef [E*T];
__device__ float  d_bias[T];
__device__ __half d_x16[(size_t)T*H];
__device__ __half d_xlo[(size_t)T*H];
__device__ __half d_w16[(size_t)E*H*H];
__device__ __half d_scratch16[(size_t)T*TOPK*H];

// ============================================================
__device__ __forceinline__ uint32_t smem_u32(const void* p) {
    uint32_t a;
    asm("{ .reg .u64 t; cvta.to.shared.u64 t, %1; cvt.u32.u64 %0, t; }"
        : "=r"(a) : "l"(p));
    return a;
}
__device__ __forceinline__ uint32_t pk(float a, float b) {
    __half2 h = __floats2half2_rn(a, b);
    return *(uint32_t*)&h;
}
__device__ __forceinline__ void ldsm4(uint32_t addr, uint32_t* r) {
    asm volatile("ldmatrix.sync.aligned.m8n8.x4.shared.b16 {%0,%1,%2,%3}, [%4];"
        : "=r"(r[0]), "=r"(r[1]), "=r"(r[2]), "=r"(r[3]) : "r"(addr));
}
__device__ __forceinline__ void ldsm4t(uint32_t addr, uint32_t* r) {
    asm volatile("ldmatrix.sync.aligned.m8n8.x4.trans.shared.b16 {%0,%1,%2,%3}, [%4];"
        : "=r"(r[0]), "=r"(r[1]), "=r"(r[2]), "=r"(r[3]) : "r"(addr));
}
__device__ __forceinline__ void mma16816(float* c, const uint32_t* a,
                                         uint32_t b0, uint32_t b1) {
    asm volatile(
        "mma.sync.aligned.m16n8k16.row.col.f32.f16.f16.f32 "
        "{%0,%1,%2,%3}, {%4,%5,%6,%7}, {%8,%9}, {%0,%1,%2,%3};\n"
        : "+f"(c[0]), "+f"(c[1]), "+f"(c[2]), "+f"(c[3])
        : "r"(a[0]), "r"(a[1]), "r"(a[2]), "r"(a[3]), "r"(b0), "r"(b1));
}
__device__ __forceinline__ void cpa16(uint32_t dst, const void* src) {
    asm volatile("cp.async.cg.shared.global [%0], [%1], 16;"
                 :: "r"(dst), "l"(src) : "memory");
}
#define CP_COMMIT() asm volatile("cp.async.commit_group;" ::: "memory")
#define CP_WAIT1()  asm volatile("cp.async.wait_group 1;"  ::: "memory")

// ============================================================
__global__ void __launch_bounds__(256) cvt_kernel(const float* __restrict__ src,
                                                  __half* __restrict__ dst) {
    if (blockIdx.x == 0 && threadIdx.x < E) d_counts[threadIdx.x] = 0;
    const size_t i = ((size_t)blockIdx.x * 256 + threadIdx.x) * 8;
    const float4 a = *(const float4*)(src + i);
    const float4 b = *(const float4*)(src + i + 4);
    uint4 u;
    u.x = pk(a.x, a.y); u.y = pk(a.z, a.w);
    u.z = pk(b.x, b.y); u.w = pk(b.z, b.w);
    *(uint4*)(dst + i) = u;
}

__global__ void __launch_bounds__(256) cvtx_kernel(const float* __restrict__ src) {
    const size_t i = ((size_t)blockIdx.x * 256 + threadIdx.x) * 8;
    float v[8];
    *(float4*)(v)     = *(const float4*)(src + i);
    *(float4*)(v + 4) = *(const float4*)(src + i + 4);
    __half hi[8];
    float  lo[8];
    #pragma unroll
    for (int j = 0; j < 8; ++j) {
        hi[j] = __float2half(v[j]);
        lo[j] = v[j] - __half2float(hi[j]);
    }
    *(uint4*)(d_x16 + i) = *(const uint4*)hi;
    uint4 ul;
    ul.x = pk(lo[0], lo[1]); ul.y = pk(lo[2], lo[3]);
    ul.z = pk(lo[4], lo[5]); ul.w = pk(lo[6], lo[7]);
    *(uint4*)(d_xlo + i) = ul;
}

// ============================================================
// Router (UNCHANGED): hi/lo-split logits MMA + fused topk.
__global__ void __launch_bounds__(256) router_kernel(const float* __restrict__ rw,
                                                     const float* __restrict__ rb)
{
    const int mBase = blockIdx.x * 128;

    extern __shared__ char dsm[];
    char* sb = dsm + ((256 - (((uintptr_t)dsm) & 255)) & 255);
    const uint32_t sbase = smem_u32(sb);
    float* larr = (float*)(sb + LTOPK);

    const int tid  = threadIdx.x;
    const int lane = tid & 31;
    const int wid  = tid >> 5;
    const int h    = lane >> 4;

    {
        const int e = tid >> 4;
        const int kb = (tid & 15) * 4;
        #pragma unroll
        for (int c = 0; c < 16; ++c) {
            const int k = c * 64 + kb;
            const float4 v = *(const float4*)(rw + e * H + k);
            const float vv[4] = {v.x, v.y, v.z, v.w};
            #pragma unroll
            for (int j = 0; j < 4; ++j) {
                const int kk = k + j;
                const uint32_t off = kk * 32
                    + ((((e >> 3) ^ ((kk >> 2) & 1))) << 4) + (e & 7) * 2;
                const __half hh = __float2half(vv[j]);
                const __half hl = __float2half(vv[j] - __half2float(hh));
                *(__half*)(sb + LBOFF + off)         = hh;
                *(__half*)(sb + LBOFF + 32768 + off) = hl;
            }
        }
    }

    const int a_row0 = tid >> 3;
    const int a_c    = tid & 7;
    const uint32_t a_dst0 = a_row0 * 128 + ((a_c ^ (a_row0 & 7)) << 4);
    const size_t a_goff = (size_t)(mBase + a_row0) * H + a_c * 8;

    const int arow = wid * 16 + (lane & 15);
    const uint32_t arowbase = sbase + arow * 128;
    const uint32_t as0 = (uint32_t)(h ^ (arow & 7));

    const int bk = lane & 15;
    const uint32_t bbase0 = sbase + LBOFF + bk * 32;
    const uint32_t bx0 = (uint32_t)(h ^ ((bk >> 2) & 1));

    __syncthreads();

    #pragma unroll
    for (int s = 0; s < 2; ++s) {
        const uint32_t so = sbase + s * LSTG;
        #pragma unroll
        for (int j = 0; j < 4; ++j) {
            cpa16(so + a_dst0 + j * 4096,         d_x16 + a_goff + (size_t)32 * j * H + s * 64);
            cpa16(so + 16384 + a_dst0 + j * 4096, d_xlo + a_goff + (size_t)32 * j * H + s * 64);
        }
        CP_COMMIT();
    }

    float c[2][4];
    #pragma unroll
    for (int nt = 0; nt < 2; ++nt)
        #pragma unroll
        for (int q = 0; q < 4; ++q) c[nt][q] = 0.f;

    int stage = 0, pstage = 2;
    for (int kt = 0; kt < 16; ++kt) {
        CP_WAIT1();
        __syncthreads();

        const int nc = kt + 2;
        if (nc < 16) {
            const uint32_t so = sbase + pstage * LSTG;
            #pragma unroll
            for (int j = 0; j < 4; ++j) {
                cpa16(so + a_dst0 + j * 4096,         d_x16 + a_goff + (size_t)32 * j * H + nc * 64);
                cpa16(so + 16384 + a_dst0 + j * 4096, d_xlo + a_goff + (size_t)32 * j * H + nc * 64);
            }
        }
        CP_COMMIT();

        const uint32_t bofs = stage * LSTG;
        #pragma unroll
        for (int g = 0; g < 4; ++g) {
            uint32_t afh[4], afl[4];
            const uint32_t aslot = (((g << 1) ^ as0) << 4);
            ldsm4(arowbase + bofs + aslot, afh);
            ldsm4(arowbase + bofs + 16384 + aslot, afl);
            const uint32_t bo = (kt * 64 + g * 16) * 32 + (bx0 << 4);
            uint32_t bh[4], bl[4];
            ldsm4t(bbase0 + bo, bh);
            ldsm4t(bbase0 + 32768 + bo, bl);
            mma16816(c[0], afh, bh[0], bh[1]);
            mma16816(c[1], afh, bh[2], bh[3]);
            mma16816(c[0], afh, bl[0], bl[1]);
            mma16816(c[1], afh, bl[2], bl[3]);
            mma16816(c[0], afl, bh[0], bh[1]);
            mma16816(c[1], afl, bh[2], bh[3]);
        }

        if (++stage == 3)  stage = 0;
        if (++pstage == 3) pstage = 0;
    }

    {
        const int r0 = wid * 16 + (lane >> 2);
        #pragma unroll
        for (int nt = 0; nt < 2; ++nt) {
            const int e0 = nt * 8 + (lane & 3) * 2;
            larr[r0 * 17 + e0]           = c[nt][0];
            larr[r0 * 17 + e0 + 1]       = c[nt][1];
            larr[(r0 + 8) * 17 + e0]     = c[nt][2];
            larr[(r0 + 8) * 17 + e0 + 1] = c[nt][3];
        }
    }
    __syncthreads();

    if (tid < 128) {
        const int t = mBase + tid;
        float pv[E];
        #pragma unroll
        for (int e = 0; e < E; ++e) pv[e] = larr[tid * 17 + e] + rb[e];

        float m = pv[0];
        #pragma unroll
        for (int e = 1; e < E; ++e) m = fmaxf(m, pv[e]);
        float Z = 0.f;
        #pragma unroll
        for (int e = 0; e < E; ++e) { pv[e] = expf(pv[e] - m); Z += pv[e]; }

        int   ids[TOPK];
        float ps [TOPK];
        float ssum = 0.f;
        #pragma unroll
        for (int k = 0; k < TOPK; ++k) {
            int best = 0; float bv = pv[0];
            #pragma unroll
            for (int e = 1; e < E; ++e)
                if (pv[e] > bv) { bv = pv[e]; best = e; }
            ids[k] = best; ps[k] = bv; pv[best] = -1.f; ssum += bv;
        }

        uint32_t mymask = 0;
        #pragma unroll
        for (int k = 0; k < TOPK; ++k) mymask |= (1u << ids[k]);

        #pragma unroll
        for (int e = 0; e < E; ++e) {
            const uint32_t vote = __ballot_sync(0xffffffffu, (mymask >> e) & 1u);
            if (vote) {
                const int leader = __ffs(vote) - 1;
                int base = 0;
                if (lane == leader) base = atomicAdd(&d_counts[e], __popc(vote));
                base = __shfl_sync(0xffffffffu, base, leader);
                if ((mymask >> e) & 1u) {
                    const int pos = base + __popc(vote & ((1u << lane) - 1u));
                    int kk = 0;
                    #pragma unroll
                    for (int k = 0; k < TOPK; ++k) if (ids[k] == e) kk = k;
                    d_perm_token[e * T + pos] = t;
                    d_perm_dest [e * T + pos] = t * TOPK + kk;
                    d_perm_coef [e * T + pos] = ps[kk] / ssum;
                }
            }
        }

        const float sn = ssum / Z;
        d_bias[t] = EPSV * sn / (sn + EPSV);
    }
}

// ============================================================
// Grouped GEMM: warp-private staging, NO CTA barrier in mainloop.
// Each warp stages its own 64xBK A tile + BKx64 B tile (dup x2 across warps).
__global__ void __launch_bounds__(128, 2) moe_gemm_kernel()
{
    const int e     = blockIdx.z;
    const int cnt   = d_counts[e];
    const int mBase = blockIdx.y * BM;
    if (mBase >= cnt) return;
    const int nBase = blockIdx.x * BN;

    const __half* Wp   = d_w16 + (size_t)e * H * H;
    const int*    ptok = d_perm_token + e * T;

    extern __shared__ char dsm[];
    char* sb = dsm + ((256 - (((uintptr_t)dsm) & 255)) & 255);
    const uint32_t sbase = smem_u32(sb);

    const int tid  = threadIdx.x;
    const int lane = tid & 31;
    const int wid  = tid >> 5;
    const int wm   = wid >> 1;      // 0..1 -> rows wm*64
    const int wn   = wid & 1;       // 0..1 -> cols wn*64

    const uint32_t wbase = sbase + wid * WREG;   // 3 stages x 8192 (A@0, B@4096)

    // ---- A staging (warp-private 64 rows x 64B): lane -> (row0=lane>>2, slot=lane&3)
    const int ar0 = lane >> 2;               // 0..7
    const int ac  = lane & 3;
    uint32_t a_off[8];                        // halfword offsets into d_x16
    #pragma unroll
    for (int j = 0; j < 8; ++j) {
        const int gm = mBase + wm * 64 + ar0 + 8 * j;
        const int tok = ptok[(gm < cnt) ? gm : (cnt - 1)];
        a_off[j] = (uint32_t)(tok * H + ac * 8);
    }
    // dst_j = a_dst0 + 512j   ((row>>1)&3 invariant under row += 8)
    const uint32_t a_dst0 = ar0 * 64 + ((ac ^ ((ar0 >> 1) & 3)) << 4);

    // ---- B staging (warp-private 32 k-rows x 128B): lane -> (k0=lane>>3, ch=lane&7)
    const int bk0 = lane >> 3;               // 0..3
    const int bch = lane & 7;
    const __half* b_src0 = Wp + (size_t)bk0 * H + nBase + wn * 64 + bch * 8;
    // dst_j = 4096 + bk0*128 + 512j + (((bch^bk0) ^ (4*(j&1)))<<4)
    const uint32_t b_x0 = (uint32_t)(bch ^ bk0) << 4;
    const uint32_t b_dst0 = 4096 + bk0 * 128;

    // ---- fragment addresses ----
    const int h = lane >> 4;
    const uint32_t as0 = (uint32_t)(h ^ (((lane & 15) >> 1) & 3));  // slot XOR base
    const uint32_t afrag0 = wbase + (lane & 15) * 64;               // + mt*1024
    // B frags: k = g*16 + (lane&15); addr = wbase+4096 + k*128 + ((ch^(k&7))<<4)
    uint32_t boff0[4];
    {
        const int k = lane & 15;
        #pragma unroll
        for (int p = 0; p < 4; ++p) {
            const int ch = p * 2 + h;
            boff0[p] = wbase + 4096 + k * 128 + ((ch ^ (k & 7)) << 4);  // + g*2048
        }
    }

    // ---- prologue: stage chunks 0,1 (warp-private; no barrier) ----
    #pragma unroll
    for (int s = 0; s < STAGES - 1; ++s) {
        const uint32_t so = wbase + s * WSTG;
        #pragma unroll
        for (int j = 0; j < 8; ++j) {
            cpa16(so + a_dst0 + j * 512, d_x16 + a_off[j] + s * BK);
            cpa16(so + b_dst0 + j * 512 + (b_x0 ^ ((j & 1) << 6)),
                  b_src0 + (size_t)(4 * j + s * BK) * H);
        }
        CP_COMMIT();
    }

    float c[4][8][4];
    #pragma unroll
    for (int mt = 0; mt < 4; ++mt)
        #pragma unroll
        for (int nt = 0; nt < 8; ++nt)
            #pragma unroll
            for (int q = 0; q < 4; ++q) c[mt][nt][q] = 0.f;

    int stage = 0, pstage = STAGES - 1;
    for (int kt = 0; kt < NCHUNK; ++kt) {
        CP_WAIT1();
        __syncwarp();

        // prefetch chunk kt+2 (warp-private)
        const int nc = kt + STAGES - 1;
        if (nc < NCHUNK) {
            const uint32_t so = wbase + pstage * WSTG;
            #pragma unroll
            for (int j = 0; j < 8; ++j) {
                cpa16(so + a_dst0 + j * 512, d_x16 + a_off[j] + nc * BK);
                cpa16(so + b_dst0 + j * 512 + (b_x0 ^ ((j & 1) << 6)),
                      b_src0 + (size_t)(4 * j + nc * BK) * H);
            }
        }
        CP_COMMIT();

        const uint32_t bofs = stage * WSTG;
        #pragma unroll
        for (int g = 0; g < 2; ++g) {
            uint32_t afr[4][4];
            const uint32_t aslot = (((g << 1) ^ as0) << 4);
            #pragma unroll
            for (int mt = 0; mt < 4; ++mt)
                ldsm4(afrag0 + mt * 1024 + bofs + aslot, afr[mt]);
            #pragma unroll
            for (int p = 0; p < 4; ++p) {
                uint32_t bfr[4];
                ldsm4t(boff0[p] + bofs + g * 2048, bfr);
                #pragma unroll
                for (int mt = 0; mt < 4; ++mt) {
                    mma16816(c[mt][p * 2 + 0], afr[mt], bfr[0], bfr[1]);
                    mma16816(c[mt][p * 2 + 1], afr[mt], bfr[2], bfr[3]);
                }
            }
        }

        if (++stage == STAGES)  stage = 0;
        if (++pstage == STAGES) pstage = 0;
    }

    // ---- epilogue: scale by coef, store fp16 rows to scratch ----
    #pragma unroll
    for (int mt = 0; mt < 4; ++mt) {
        #pragma unroll
        for (int half = 0; half < 2; ++half) {
            const int r  = wm * 64 + mt * 16 + (lane >> 2) + half * 8;
            const int gm = mBase + r;
            if (gm < cnt) {
                const int   dest = d_perm_dest[e * T + gm];
                const float coef = d_perm_coef[e * T + gm];
                __half* orow = d_scratch16 + (size_t)dest * H + nBase;
                #pragma unroll
                for (int nt = 0; nt < 8; ++nt) {
                    const int col = wn * 64 + nt * 8 + (lane & 3) * 2;
                    *(uint32_t*)(orow + col) =
                        pk(c[mt][nt][half * 2 + 0] * coef,
                           c[mt][nt][half * 2 + 1] * coef);
                }
            }
        }
    }
}

// ============================================================
__global__ void __launch_bounds__(256) reduce_kernel(float* __restrict__ out)
{
    const int gid = blockIdx.x * blockDim.x + threadIdx.x;
    const int t   = gid >> 7;
    const int c8  = gid & 127;
    const __half* base = d_scratch16 + (size_t)t * TOPK * H + c8 * 8;

    float acc[8];
    #pragma unroll
    for (int j = 0; j < 8; ++j) acc[j] = 0.f;
    #pragma unroll
    for (int k = 0; k < TOPK; ++k) {
        const uint4 v = *(const uint4*)(base + (size_t)k * H);
        const uint32_t w[4] = {v.x, v.y, v.z, v.w};
        #pragma unroll
        for (int j = 0; j < 4; ++j) {
            const float2 f = __half22float2(*(const __half2*)&w[j]);
            acc[j * 2 + 0] += f.x;
            acc[j * 2 + 1] += f.y;
        }
    }
    const float bi = d_bias[t];
    float* op = out + (size_t)t * H + c8 * 8;
    float4 o0, o1;
    o0.x = acc[0] + bi; o0.y = acc[1] + bi; o0.z = acc[2] + bi; o0.w = acc[3] + bi;
    o1.x = acc[4] + bi; o1.y = acc[5] + bi; o1.z = acc[6] + bi; o1.w = acc[7] + bi;
    *(float4*)(op)     = o0;
    *(float4*)(op + 4) = o1;
}

// ============================================================
extern "C" void kernel_launch(void* const* d_in, const int* in_sizes, int n_in,
                              void* d_out, int out_size)
{
    const float* tokens = (const float*)d_in[0];
    const float* rw     = (const float*)d_in[1];
    const float* rb     = (const float*)d_in[2];
    const float* ew     = (const float*)d_in[3];
    float* out = (float*)d_out;

    cudaFuncSetAttribute(moe_gemm_kernel,
                         cudaFuncAttributeMaxDynamicSharedMemorySize, DSMEM);
    cudaFuncSetAttribute(router_kernel,
                         cudaFuncAttributeMaxDynamicSharedMemorySize, LDSMEM);

    __half* w16p; cudaGetSymbolAddress((void**)&w16p, d_w16);

    cvt_kernel<<<(int)(((size_t)E * H * H) / (256 * 8)), 256>>>(ew, w16p);
    cvtx_kernel<<<(int)(((size_t)T * H) / (256 * 8)), 256>>>(tokens);
    router_kernel<<<T / 128, 256, LDSMEM>>>(rw, rb);
    dim3 g(H / BN, T / BM, E);
    moe_gemm_kernel<<<g, 128, DSMEM>>>();
    reduce_kernel<<<(T * H / 8) / 256, 256>>>(out);
}

// round 14
// speedup vs baseline: 1.0476x; 1.0476x over previous
#include <cuda_runtime.h>
#include <cuda_fp16.h>
#include <cstdint>
#include <math.h>

#define H      1024
#define E      16
#define T      8192
#define TOPK   6
#define EPSV   1e-10f

// ---- main GEMM: BM=128, BN=128, BK=64; 128 thr, 4 warps (2x2), warptile 64x64
#define BM 128
#define BN 128
#define BK 64
#define NCHUNK (H/BK)           // 16
#define STAGES 3
#define ASTG (128*128)          // 16384
#define BSTG (64*256)           // 16384
#define STGB (ASTG+BSTG)        // 32768
#define DSMEM (STAGES*STGB + 256)

// ---- router mini-GEMM (hi/lo split) + fused topk ----
#define LSTG   32768
#define LBOFF  (3*LSTG)
#define LTOPK  (LBOFF + 2*32768)
#define LDSMEM (LTOPK + 128*17*4 + 256)

// ---- device globals ----
__device__ int    d_counts[E];
__device__ int    d_perm_token[E*T];
__device__ int    d_perm_dest [E*T];
__device__ float  d_perm_coef [E*T];
__device__ float  d_bias[T];
__device__ __half d_x16[(size_t)T*H];
__device__ __half d_xlo[(size_t)T*H];
__device__ __half d_w16[(size_t)E*H*H];
__device__ __half d_scratch16[(size_t)T*TOPK*H];

// ============================================================
__device__ __forceinline__ uint32_t smem_u32(const void* p) {
    uint32_t a;
    asm("{ .reg .u64 t; cvta.to.shared.u64 t, %1; cvt.u32.u64 %0, t; }"
        : "=r"(a) : "l"(p));
    return a;
}
__device__ __forceinline__ uint32_t pk(float a, float b) {
    __half2 h = __floats2half2_rn(a, b);
    return *(uint32_t*)&h;
}
__device__ __forceinline__ void ldsm4(uint32_t addr, uint32_t* r) {
    asm volatile("ldmatrix.sync.aligned.m8n8.x4.shared.b16 {%0,%1,%2,%3}, [%4];"
        : "=r"(r[0]), "=r"(r[1]), "=r"(r[2]), "=r"(r[3]) : "r"(addr));
}
__device__ __forceinline__ void ldsm4t(uint32_t addr, uint32_t* r) {
    asm volatile("ldmatrix.sync.aligned.m8n8.x4.trans.shared.b16 {%0,%1,%2,%3}, [%4];"
        : "=r"(r[0]), "=r"(r[1]), "=r"(r[2]), "=r"(r[3]) : "r"(addr));
}
__device__ __forceinline__ void mma16816(float* c, const uint32_t* a,
                                         uint32_t b0, uint32_t b1) {
    asm volatile(
        "mma.sync.aligned.m16n8k16.row.col.f32.f16.f16.f32 "
        "{%0,%1,%2,%3}, {%4,%5,%6,%7}, {%8,%9}, {%0,%1,%2,%3};\n"
        : "+f"(c[0]), "+f"(c[1]), "+f"(c[2]), "+f"(c[3])
        : "r"(a[0]), "r"(a[1]), "r"(a[2]), "r"(a[3]), "r"(b0), "r"(b1));
}
__device__ __forceinline__ void cpa16(uint32_t dst, const void* src) {
    asm volatile("cp.async.cg.shared.global [%0], [%1], 16;"
                 :: "r"(dst), "l"(src) : "memory");
}
#define CP_COMMIT() asm volatile("cp.async.commit_group;" ::: "memory")
#define CP_WAIT1()  asm volatile("cp.async.wait_group 1;"  ::: "memory")

// ============================================================
// Merged conversion kernel: blocks [0, WB) convert W, blocks [WB, WB+XB) do
// x -> hi/lo. Block 0 zeroes counts.
#define WB ((int)(((size_t)E*H*H) / (256*8)))   // 8192
#define XB ((int)(((size_t)T*H)   / (256*8)))   // 4096

__global__ void __launch_bounds__(256) cvt_all_kernel(const float* __restrict__ ew,
                                                      const float* __restrict__ tokens) {
    if (blockIdx.x == 0 && threadIdx.x < E) d_counts[threadIdx.x] = 0;
    if (blockIdx.x < WB) {
        const size_t i = ((size_t)blockIdx.x * 256 + threadIdx.x) * 8;
        const float4 a = *(const float4*)(ew + i);
        const float4 b = *(const float4*)(ew + i + 4);
        uint4 u;
        u.x = pk(a.x, a.y); u.y = pk(a.z, a.w);
        u.z = pk(b.x, b.y); u.w = pk(b.z, b.w);
        *(uint4*)(d_w16 + i) = u;
    } else {
        const size_t i = ((size_t)(blockIdx.x - WB) * 256 + threadIdx.x) * 8;
        float v[8];
        *(float4*)(v)     = *(const float4*)(tokens + i);
        *(float4*)(v + 4) = *(const float4*)(tokens + i + 4);
        __half hi[8];
        float  lo[8];
        #pragma unroll
        for (int j = 0; j < 8; ++j) {
            hi[j] = __float2half(v[j]);
            lo[j] = v[j] - __half2float(hi[j]);
        }
        *(uint4*)(d_x16 + i) = *(const uint4*)hi;
        uint4 ul;
        ul.x = pk(lo[0], lo[1]); ul.y = pk(lo[2], lo[3]);
        ul.z = pk(lo[4], lo[5]); ul.w = pk(lo[6], lo[7]);
        *(uint4*)(d_xlo + i) = ul;
    }
}

// ============================================================
// Router (UNCHANGED from R11/R12): hi/lo-split logits MMA + fused topk.
__global__ void __launch_bounds__(256) router_kernel(const float* __restrict__ rw,
                                                     const float* __restrict__ rb)
{
    const int mBase = blockIdx.x * 128;

    extern __shared__ char dsm[];
    char* sb = dsm + ((256 - (((uintptr_t)dsm) & 255)) & 255);
    const uint32_t sbase = smem_u32(sb);
    float* larr = (float*)(sb + LTOPK);

    const int tid  = threadIdx.x;
    const int lane = tid & 31;
    const int wid  = tid >> 5;
    const int h    = lane >> 4;

    {
        const int e = tid >> 4;
        const int kb = (tid & 15) * 4;
        #pragma unroll
        for (int c = 0; c < 16; ++c) {
            const int k = c * 64 + kb;
            const float4 v = *(const float4*)(rw + e * H + k);
            const float vv[4] = {v.x, v.y, v.z, v.w};
            #pragma unroll
            for (int j = 0; j < 4; ++j) {
                const int kk = k + j;
                const uint32_t off = kk * 32
                    + ((((e >> 3) ^ ((kk >> 2) & 1))) << 4) + (e & 7) * 2;
                const __half hh = __float2half(vv[j]);
                const __half hl = __float2half(vv[j] - __half2float(hh));
                *(__half*)(sb + LBOFF + off)         = hh;
                *(__half*)(sb + LBOFF + 32768 + off) = hl;
            }
        }
    }

    const int a_row0 = tid >> 3;
    const int a_c    = tid & 7;
    const uint32_t a_dst0 = a_row0 * 128 + ((a_c ^ (a_row0 & 7)) << 4);
    const size_t a_goff = (size_t)(mBase + a_row0) * H + a_c * 8;

    const int arow = wid * 16 + (lane & 15);
    const uint32_t arowbase = sbase + arow * 128;
    const uint32_t as0 = (uint32_t)(h ^ (arow & 7));

    const int bk = lane & 15;
    const uint32_t bbase0 = sbase + LBOFF + bk * 32;
    const uint32_t bx0 = (uint32_t)(h ^ ((bk >> 2) & 1));

    __syncthreads();

    #pragma unroll
    for (int s = 0; s < 2; ++s) {
        const uint32_t so = sbase + s * LSTG;
        #pragma unroll
        for (int j = 0; j < 4; ++j) {
            cpa16(so + a_dst0 + j * 4096,         d_x16 + a_goff + (size_t)32 * j * H + s * 64);
            cpa16(so + 16384 + a_dst0 + j * 4096, d_xlo + a_goff + (size_t)32 * j * H + s * 64);
        }
        CP_COMMIT();
    }

    float c[2][4];
    #pragma unroll
    for (int nt = 0; nt < 2; ++nt)
        #pragma unroll
        for (int q = 0; q < 4; ++q) c[nt][q] = 0.f;

    int stage = 0, pstage = 2;
    for (int kt = 0; kt < 16; ++kt) {
        CP_WAIT1();
        __syncthreads();

        const int nc = kt + 2;
        if (nc < 16) {
            const uint32_t so = sbase + pstage * LSTG;
            #pragma unroll
            for (int j = 0; j < 4; ++j) {
                cpa16(so + a_dst0 + j * 4096,         d_x16 + a_goff + (size_t)32 * j * H + nc * 64);
                cpa16(so + 16384 + a_dst0 + j * 4096, d_xlo + a_goff + (size_t)32 * j * H + nc * 64);
            }
        }
        CP_COMMIT();

        const uint32_t bofs = stage * LSTG;
        #pragma unroll
        for (int g = 0; g < 4; ++g) {
            uint32_t afh[4], afl[4];
            const uint32_t aslot = (((g << 1) ^ as0) << 4);
            ldsm4(arowbase + bofs + aslot, afh);
            ldsm4(arowbase + bofs + 16384 + aslot, afl);
            const uint32_t bo = (kt * 64 + g * 16) * 32 + (bx0 << 4);
            uint32_t bh[4], bl[4];
            ldsm4t(bbase0 + bo, bh);
            ldsm4t(bbase0 + 32768 + bo, bl);
            mma16816(c[0], afh, bh[0], bh[1]);
            mma16816(c[1], afh, bh[2], bh[3]);
            mma16816(c[0], afh, bl[0], bl[1]);
            mma16816(c[1], afh, bl[2], bl[3]);
            mma16816(c[0], afl, bh[0], bh[1]);
            mma16816(c[1], afl, bh[2], bh[3]);
        }

        if (++stage == 3)  stage = 0;
        if (++pstage == 3) pstage = 0;
    }

    {
        const int r0 = wid * 16 + (lane >> 2);
        #pragma unroll
        for (int nt = 0; nt < 2; ++nt) {
            const int e0 = nt * 8 + (lane & 3) * 2;
            larr[r0 * 17 + e0]           = c[nt][0];
            larr[r0 * 17 + e0 + 1]       = c[nt][1];
            larr[(r0 + 8) * 17 + e0]     = c[nt][2];
            larr[(r0 + 8) * 17 + e0 + 1] = c[nt][3];
        }
    }
    __syncthreads();

    if (tid < 128) {
        const int t = mBase + tid;
        float pv[E];
        #pragma unroll
        for (int e = 0; e < E; ++e) pv[e] = larr[tid * 17 + e] + rb[e];

        float m = pv[0];
        #pragma unroll
        for (int e = 1; e < E; ++e) m = fmaxf(m, pv[e]);
        float Z = 0.f;
        #pragma unroll
        for (int e = 0; e < E; ++e) { pv[e] = expf(pv[e] - m); Z += pv[e]; }

        int   ids[TOPK];
        float ps [TOPK];
        float ssum = 0.f;
        #pragma unroll
        for (int k = 0; k < TOPK; ++k) {
            int best = 0; float bv = pv[0];
            #pragma unroll
            for (int e = 1; e < E; ++e)
                if (pv[e] > bv) { bv = pv[e]; best = e; }
            ids[k] = best; ps[k] = bv; pv[best] = -1.f; ssum += bv;
        }

        uint32_t mymask = 0;
        #pragma unroll
        for (int k = 0; k < TOPK; ++k) mymask |= (1u << ids[k]);

        #pragma unroll
        for (int e = 0; e < E; ++e) {
            const uint32_t vote = __ballot_sync(0xffffffffu, (mymask >> e) & 1u);
            if (vote) {
                const int leader = __ffs(vote) - 1;
                int base = 0;
                if (lane == leader) base = atomicAdd(&d_counts[e], __popc(vote));
                base = __shfl_sync(0xffffffffu, base, leader);
                if ((mymask >> e) & 1u) {
                    const int pos = base + __popc(vote & ((1u << lane) - 1u));
                    int kk = 0;
                    #pragma unroll
                    for (int k = 0; k < TOPK; ++k) if (ids[k] == e) kk = k;
                    d_perm_token[e * T + pos] = t;
                    d_perm_dest [e * T + pos] = t * TOPK + kk;
                    d_perm_coef [e * T + pos] = ps[kk] / ssum;
                }
            }
        }

        const float sn = ssum / Z;
        d_bias[t] = EPSV * sn / (sn + EPSV);
    }
}

// ============================================================
// Grouped GEMM (R12 geometry): 128 thr, 4 warps (2x2), warptile 64x64,
// BK=64, 3-stage cp.async, CTA barrier per chunk.
// Inner loop: B frags loaded 2 p's at a time -> longer MMA runs.
__global__ void __launch_bounds__(128, 2) moe_gemm_kernel()
{
    const int e     = blockIdx.z;
    const int cnt   = d_counts[e];
    const int mBase = blockIdx.y * BM;
    if (mBase >= cnt) return;
    const int nBase = blockIdx.x * BN;

    const __half* Wp   = d_w16 + (size_t)e * H * H;
    const int*    ptok = d_perm_token + e * T;

    extern __shared__ char dsm[];
    char* sb = dsm + ((256 - (((uintptr_t)dsm) & 255)) & 255);
    const uint32_t sbase = smem_u32(sb);

    const int tid  = threadIdx.x;
    const int lane = tid & 31;
    const int wid  = tid >> 5;
    const int wm   = wid >> 1;
    const int wn   = wid & 1;

    const int a_row0 = tid >> 3;               // 0..15
    const int a_c    = tid & 7;
    const uint32_t a_dst0 = a_row0 * 128 + ((a_c ^ (a_row0 & 7)) << 4);
    uint32_t a_off[8];
    #pragma unroll
    for (int j = 0; j < 8; ++j) {
        const int gm = mBase + a_row0 + 16 * j;
        const int tok = ptok[(gm < cnt) ? gm : (cnt - 1)];
        a_off[j] = (uint32_t)(tok * H + a_c * 8);
    }
    const int b_k0 = tid >> 4;                 // 0..7
    const int b_ch = tid & 15;
    const uint32_t b_dst0 = ASTG + b_k0 * 256 + ((b_ch ^ (b_k0 & 7)) << 4);
    const __half* b_src0 = Wp + (size_t)b_k0 * H + nBase + b_ch * 8;

    const int h = lane >> 4;
    const uint32_t as0 = (uint32_t)(h ^ (lane & 7));
    const uint32_t arowbase0 = sbase + (wm * 64 + (lane & 15)) * 128;
    uint32_t boff0[4];
    {
        const int k = lane & 15;
        #pragma unroll
        for (int p = 0; p < 4; ++p) {
            const int ch = wn * 8 + p * 2 + h;
            boff0[p] = sbase + ASTG + k * 256 + ((ch ^ (k & 7)) << 4);
        }
    }

    #pragma unroll
    for (int s = 0; s < STAGES - 1; ++s) {
        const uint32_t so = sbase + s * STGB;
        #pragma unroll
        for (int j = 0; j < 8; ++j) {
            cpa16(so + a_dst0 + j * 2048, d_x16 + a_off[j] + s * BK);
            cpa16(so + b_dst0 + j * 2048, b_src0 + (size_t)(8 * j + s * BK) * H);
        }
        CP_COMMIT();
    }

    float c[4][8][4];
    #pragma unroll
    for (int mt = 0; mt < 4; ++mt)
        #pragma unroll
        for (int nt = 0; nt < 8; ++nt)
            #pragma unroll
            for (int q = 0; q < 4; ++q) c[mt][nt][q] = 0.f;

    int stage = 0, pstage = STAGES - 1;
    for (int kt = 0; kt < NCHUNK; ++kt) {
        CP_WAIT1();
        __syncthreads();

        const int nc = kt + STAGES - 1;
        if (nc < NCHUNK) {
            const uint32_t so = sbase + pstage * STGB;
            #pragma unroll
            for (int j = 0; j < 8; ++j) {
                cpa16(so + a_dst0 + j * 2048, d_x16 + a_off[j] + nc * BK);
                cpa16(so + b_dst0 + j * 2048, b_src0 + (size_t)(8 * j + nc * BK) * H);
            }
        }
        CP_COMMIT();

        const uint32_t bofs = stage * STGB;
        #pragma unroll
        for (int g = 0; g < 4; ++g) {
            uint32_t afr[4][4];
            const uint32_t aslot = (((g << 1) ^ as0) << 4);
            #pragma unroll
            for (int mt = 0; mt < 4; ++mt)
                ldsm4(arowbase0 + mt * 2048 + bofs + aslot, afr[mt]);
            // two p's per LDSM batch -> 16-MMA runs between dependent loads
            #pragma unroll
            for (int pp = 0; pp < 2; ++pp) {
                uint32_t bfr[2][4];
                ldsm4t(boff0[pp * 2 + 0] + bofs + g * 4096, bfr[0]);
                ldsm4t(boff0[pp * 2 + 1] + bofs + g * 4096, bfr[1]);
                #pragma unroll
                for (int q = 0; q < 2; ++q) {
                    const int p = pp * 2 + q;
                    #pragma unroll
                    for (int mt = 0; mt < 4; ++mt) {
                        mma16816(c[mt][p * 2 + 0], afr[mt], bfr[q][0], bfr[q][1]);
                        mma16816(c[mt][p * 2 + 1], afr[mt], bfr[q][2], bfr[q][3]);
                    }
                }
            }
        }

        if (++stage == STAGES)  stage = 0;
        if (++pstage == STAGES) pstage = 0;
    }

    #pragma unroll
    for (int mt = 0; mt < 4; ++mt) {
        #pragma unroll
        for (int half = 0; half < 2; ++half) {
            const int r  = wm * 64 + mt * 16 + (lane >> 2) + half * 8;
            const int gm = mBase + r;
            if (gm < cnt) {
                const int   dest = d_perm_dest[e * T + gm];
                const float coef = d_perm_coef[e * T + gm];
                __half* orow = d_scratch16 + (size_t)dest * H + nBase;
                #pragma unroll
                for (int nt = 0; nt < 8; ++nt) {
                    const int col = wn * 64 + nt * 8 + (lane & 3) * 2;
                    *(uint32_t*)(orow + col) =
                        pk(c[mt][nt][half * 2 + 0] * coef,
                           c[mt][nt][half * 2 + 1] * coef);
                }
            }
        }
    }
}

// ============================================================
// Reduce: 16 elems/thread (doubled MLP). out = sum_k scratch + bias.
__global__ void __launch_bounds__(256) reduce_kernel(float* __restrict__ out)
{
    const int gid = blockIdx.x * blockDim.x + threadIdx.x;
    const int t   = gid >> 6;                 // H/16 = 64 per token
    const int c16 = gid & 63;
    const __half* base = d_scratch16 + (size_t)t * TOPK * H + c16 * 16;

    float acc[16];
    #pragma unroll
    for (int j = 0; j < 16; ++j) acc[j] = 0.f;
    #pragma unroll
    for (int k = 0; k < TOPK; ++k) {
        const uint4 v0 = *(const uint4*)(base + (size_t)k * H);
        const uint4 v1 = *(const uint4*)(base + (size_t)k * H + 8);
        const uint32_t w[8] = {v0.x, v0.y, v0.z, v0.w, v1.x, v1.y, v1.z, v1.w};
        #pragma unroll
        for (int j = 0; j < 8; ++j) {
            const float2 f = __half22float2(*(const __half2*)&w[j]);
            acc[j * 2 + 0] += f.x;
            acc[j * 2 + 1] += f.y;
        }
    }
    const float bi = d_bias[t];
    float* op = out + (size_t)t * H + c16 * 16;
    #pragma unroll
    for (int j = 0; j < 4; ++j) {
        float4 o;
        o.x = acc[j * 4 + 0] + bi; o.y = acc[j * 4 + 1] + bi;
        o.z = acc[j * 4 + 2] + bi; o.w = acc[j * 4 + 3] + bi;
        *(float4*)(op + j * 4) = o;
    }
}

// ============================================================
extern "C" void kernel_launch(void* const* d_in, const int* in_sizes, int n_in,
                              void* d_out, int out_size)
{
    const float* tokens = (const float*)d_in[0];
    const float* rw     = (const float*)d_in[1];
    const float* rb     = (const float*)d_in[2];
    const float* ew     = (const float*)d_in[3];
    float* out = (float*)d_out;

    cudaFuncSetAttribute(moe_gemm_kernel,
                         cudaFuncAttributeMaxDynamicSharedMemorySize, DSMEM);
    cudaFuncSetAttribute(router_kernel,
                         cudaFuncAttributeMaxDynamicSharedMemorySize, LDSMEM);

    cvt_all_kernel<<<WB + XB, 256>>>(ew, tokens);
    router_kernel<<<T / 128, 256, LDSMEM>>>(rw, rb);
    dim3 g(H / BN, T / BM, E);
    moe_gemm_kernel<<<g, 128, DSMEM>>>();
    reduce_kernel<<<(T * H / 16) / 256, 256>>>(out);
}

// round 15
// speedup vs baseline: 1.0656x; 1.0172x over previous
#include <cuda_runtime.h>
#include <cuda_fp16.h>
#include <cstdint>
#include <math.h>

#define H      1024
#define E      16
#define T      8192
#define TOPK   6
#define EPSV   1e-10f

// ---- main GEMM: BM=128, BN=128, BK=64; 128 thr, 4 warps (2x2), warptile 64x64
#define BM 128
#define BN 128
#define BK 64
#define NCHUNK (H/BK)           // 16
#define STAGES 3
#define ASTG (128*128)          // 16384
#define BSTG (64*256)           // 16384
#define STGB (ASTG+BSTG)        // 32768
#define DSMEM (STAGES*STGB + 256)

// ---- router mini-GEMM (hi/lo split) + fused topk ----
#define LSTG   32768
#define LBOFF  (3*LSTG)
#define LTOPK  (LBOFF + 2*32768)
#define LDSMEM (LTOPK + 128*17*4 + 256)

// ---- device globals ----
__device__ int    d_counts[E];
__device__ int    d_perm_token[E*T];
__device__ int    d_perm_dest [E*T];
__device__ float  d_perm_coef [E*T];
__device__ float  d_bias[T];
__device__ __half d_x16[(size_t)T*H];
__device__ __half d_xlo[(size_t)T*H];
__device__ __half d_w16[(size_t)E*H*H];
__device__ __half d_scratch16[(size_t)T*TOPK*H];

// ============================================================
__device__ __forceinline__ uint32_t smem_u32(const void* p) {
    uint32_t a;
    asm("{ .reg .u64 t; cvta.to.shared.u64 t, %1; cvt.u32.u64 %0, t; }"
        : "=r"(a) : "l"(p));
    return a;
}
__device__ __forceinline__ uint32_t pk(float a, float b) {
    __half2 h = __floats2half2_rn(a, b);
    return *(uint32_t*)&h;
}
__device__ __forceinline__ void ldsm4(uint32_t addr, uint32_t* r) {
    asm volatile("ldmatrix.sync.aligned.m8n8.x4.shared.b16 {%0,%1,%2,%3}, [%4];"
        : "=r"(r[0]), "=r"(r[1]), "=r"(r[2]), "=r"(r[3]) : "r"(addr));
}
__device__ __forceinline__ void ldsm4t(uint32_t addr, uint32_t* r) {
    asm volatile("ldmatrix.sync.aligned.m8n8.x4.trans.shared.b16 {%0,%1,%2,%3}, [%4];"
        : "=r"(r[0]), "=r"(r[1]), "=r"(r[2]), "=r"(r[3]) : "r"(addr));
}
__device__ __forceinline__ void mma16816(float* c, const uint32_t* a,
                                         uint32_t b0, uint32_t b1) {
    asm volatile(
        "mma.sync.aligned.m16n8k16.row.col.f32.f16.f16.f32 "
        "{%0,%1,%2,%3}, {%4,%5,%6,%7}, {%8,%9}, {%0,%1,%2,%3};\n"
        : "+f"(c[0]), "+f"(c[1]), "+f"(c[2]), "+f"(c[3])
        : "r"(a[0]), "r"(a[1]), "r"(a[2]), "r"(a[3]), "r"(b0), "r"(b1));
}
__device__ __forceinline__ void cpa16(uint32_t dst, const void* src) {
    asm volatile("cp.async.cg.shared.global [%0], [%1], 16;"
                 :: "r"(dst), "l"(src) : "memory");
}
#define CP_COMMIT() asm volatile("cp.async.commit_group;" ::: "memory")
#define CP_WAIT1()  asm volatile("cp.async.wait_group 1;"  ::: "memory")

// ============================================================
// Merged conversion kernel: blocks [0, WB) convert W, blocks [WB, WB+XB) do
// x -> hi/lo. Block 0 zeroes counts.
#define WB ((int)(((size_t)E*H*H) / (256*8)))   // 8192
#define XB ((int)(((size_t)T*H)   / (256*8)))   // 4096

__global__ void __launch_bounds__(256) cvt_all_kernel(const float* __restrict__ ew,
                                                      const float* __restrict__ tokens) {
    if (blockIdx.x == 0 && threadIdx.x < E) d_counts[threadIdx.x] = 0;
    if (blockIdx.x < WB) {
        const size_t i = ((size_t)blockIdx.x * 256 + threadIdx.x) * 8;
        const float4 a = *(const float4*)(ew + i);
        const float4 b = *(const float4*)(ew + i + 4);
        uint4 u;
        u.x = pk(a.x, a.y); u.y = pk(a.z, a.w);
        u.z = pk(b.x, b.y); u.w = pk(b.z, b.w);
        *(uint4*)(d_w16 + i) = u;
    } else {
        const size_t i = ((size_t)(blockIdx.x - WB) * 256 + threadIdx.x) * 8;
        float v[8];
        *(float4*)(v)     = *(const float4*)(tokens + i);
        *(float4*)(v + 4) = *(const float4*)(tokens + i + 4);
        __half hi[8];
        float  lo[8];
        #pragma unroll
        for (int j = 0; j < 8; ++j) {
            hi[j] = __float2half(v[j]);
            lo[j] = v[j] - __half2float(hi[j]);
        }
        *(uint4*)(d_x16 + i) = *(const uint4*)hi;
        uint4 ul;
        ul.x = pk(lo[0], lo[1]); ul.y = pk(lo[2], lo[3]);
        ul.z = pk(lo[4], lo[5]); ul.w = pk(lo[6], lo[7]);
        *(uint4*)(d_xlo + i) = ul;
    }
}

// ============================================================
// Router: hi/lo-split logits MMA + fused softmax/topk/scatter.
__global__ void __launch_bounds__(256) router_kernel(const float* __restrict__ rw,
                                                     const float* __restrict__ rb)
{
    const int mBase = blockIdx.x * 128;

    extern __shared__ char dsm[];
    char* sb = dsm + ((256 - (((uintptr_t)dsm) & 255)) & 255);
    const uint32_t sbase = smem_u32(sb);
    float* larr = (float*)(sb + LTOPK);

    const int tid  = threadIdx.x;
    const int lane = tid & 31;
    const int wid  = tid >> 5;
    const int h    = lane >> 4;

    {
        const int e = tid >> 4;
        const int kb = (tid & 15) * 4;
        #pragma unroll
        for (int c = 0; c < 16; ++c) {
            const int k = c * 64 + kb;
            const float4 v = *(const float4*)(rw + e * H + k);
            const float vv[4] = {v.x, v.y, v.z, v.w};
            #pragma unroll
            for (int j = 0; j < 4; ++j) {
                const int kk = k + j;
                const uint32_t off = kk * 32
                    + ((((e >> 3) ^ ((kk >> 2) & 1))) << 4) + (e & 7) * 2;
                const __half hh = __float2half(vv[j]);
                const __half hl = __float2half(vv[j] - __half2float(hh));
                *(__half*)(sb + LBOFF + off)         = hh;
                *(__half*)(sb + LBOFF + 32768 + off) = hl;
            }
        }
    }

    const int a_row0 = tid >> 3;
    const int a_c    = tid & 7;
    const uint32_t a_dst0 = a_row0 * 128 + ((a_c ^ (a_row0 & 7)) << 4);
    const size_t a_goff = (size_t)(mBase + a_row0) * H + a_c * 8;

    const int arow = wid * 16 + (lane & 15);
    const uint32_t arowbase = sbase + arow * 128;
    const uint32_t as0 = (uint32_t)(h ^ (arow & 7));

    const int bk = lane & 15;
    const uint32_t bbase0 = sbase + LBOFF + bk * 32;
    const uint32_t bx0 = (uint32_t)(h ^ ((bk >> 2) & 1));

    __syncthreads();

    #pragma unroll
    for (int s = 0; s < 2; ++s) {
        const uint32_t so = sbase + s * LSTG;
        #pragma unroll
        for (int j = 0; j < 4; ++j) {
            cpa16(so + a_dst0 + j * 4096,         d_x16 + a_goff + (size_t)32 * j * H + s * 64);
            cpa16(so + 16384 + a_dst0 + j * 4096, d_xlo + a_goff + (size_t)32 * j * H + s * 64);
        }
        CP_COMMIT();
    }

    float c[2][4];
    #pragma unroll
    for (int nt = 0; nt < 2; ++nt)
        #pragma unroll
        for (int q = 0; q < 4; ++q) c[nt][q] = 0.f;

    int stage = 0, pstage = 2;
    for (int kt = 0; kt < 16; ++kt) {
        CP_WAIT1();
        __syncthreads();

        const int nc = kt + 2;
        if (nc < 16) {
            const uint32_t so = sbase + pstage * LSTG;
            #pragma unroll
            for (int j = 0; j < 4; ++j) {
                cpa16(so + a_dst0 + j * 4096,         d_x16 + a_goff + (size_t)32 * j * H + nc * 64);
                cpa16(so + 16384 + a_dst0 + j * 4096, d_xlo + a_goff + (size_t)32 * j * H + nc * 64);
            }
        }
        CP_COMMIT();

        const uint32_t bofs = stage * LSTG;
        #pragma unroll
        for (int g = 0; g < 4; ++g) {
            uint32_t afh[4], afl[4];
            const uint32_t aslot = (((g << 1) ^ as0) << 4);
            ldsm4(arowbase + bofs + aslot, afh);
            ldsm4(arowbase + bofs + 16384 + aslot, afl);
            const uint32_t bo = (kt * 64 + g * 16) * 32 + (bx0 << 4);
            uint32_t bh[4], bl[4];
            ldsm4t(bbase0 + bo, bh);
            ldsm4t(bbase0 + 32768 + bo, bl);
            mma16816(c[0], afh, bh[0], bh[1]);
            mma16816(c[1], afh, bh[2], bh[3]);
            mma16816(c[0], afh, bl[0], bl[1]);
            mma16816(c[1], afh, bl[2], bl[3]);
            mma16816(c[0], afl, bh[0], bh[1]);
            mma16816(c[1], afl, bh[2], bh[3]);
        }

        if (++stage == 3)  stage = 0;
        if (++pstage == 3) pstage = 0;
    }

    {
        const int r0 = wid * 16 + (lane >> 2);
        #pragma unroll
        for (int nt = 0; nt < 2; ++nt) {
            const int e0 = nt * 8 + (lane & 3) * 2;
            larr[r0 * 17 + e0]           = c[nt][0];
            larr[r0 * 17 + e0 + 1]       = c[nt][1];
            larr[(r0 + 8) * 17 + e0]     = c[nt][2];
            larr[(r0 + 8) * 17 + e0 + 1] = c[nt][3];
        }
    }
    __syncthreads();

    if (tid < 128) {
        const int t = mBase + tid;
        float pv[E];
        #pragma unroll
        for (int e = 0; e < E; ++e) pv[e] = larr[tid * 17 + e] + rb[e];

        float m = pv[0];
        #pragma unroll
        for (int e = 1; e < E; ++e) m = fmaxf(m, pv[e]);
        float Z = 0.f;
        #pragma unroll
        for (int e = 0; e < E; ++e) { pv[e] = expf(pv[e] - m); Z += pv[e]; }

        int   ids[TOPK];
        float ps [TOPK];
        float ssum = 0.f;
        #pragma unroll
        for (int k = 0; k < TOPK; ++k) {
            int best = 0; float bv = pv[0];
            #pragma unroll
            for (int e = 1; e < E; ++e)
                if (pv[e] > bv) { bv = pv[e]; best = e; }
            ids[k] = best; ps[k] = bv; pv[best] = -1.f; ssum += bv;
        }

        uint32_t mymask = 0;
        #pragma unroll
        for (int k = 0; k < TOPK; ++k) mymask |= (1u << ids[k]);

        #pragma unroll
        for (int e = 0; e < E; ++e) {
            const uint32_t vote = __ballot_sync(0xffffffffu, (mymask >> e) & 1u);
            if (vote) {
                const int leader = __ffs(vote) - 1;
                int base = 0;
                if (lane == leader) base = atomicAdd(&d_counts[e], __popc(vote));
                base = __shfl_sync(0xffffffffu, base, leader);
                if ((mymask >> e) & 1u) {
                    const int pos = base + __popc(vote & ((1u << lane) - 1u));
                    int kk = 0;
                    #pragma unroll
                    for (int k = 0; k < TOPK; ++k) if (ids[k] == e) kk = k;
                    d_perm_token[e * T + pos] = t;
                    d_perm_dest [e * T + pos] = t * TOPK + kk;
                    d_perm_coef [e * T + pos] = ps[kk] / ssum;
                }
            }
        }

        const float sn = ssum / Z;
        d_bias[t] = EPSV * sn / (sn + EPSV);
    }
}

// ============================================================
// Grouped GEMM (R12 geometry, R14 inner order): 128 thr, 4 warps (2x2),
// warptile 64x64, BK=64, 3-stage cp.async.
__global__ void __launch_bounds__(128, 2) moe_gemm_kernel()
{
    const int e     = blockIdx.z;
    const int cnt   = d_counts[e];
    const int mBase = blockIdx.y * BM;
    if (mBase >= cnt) return;
    const int nBase = blockIdx.x * BN;

    const __half* Wp   = d_w16 + (size_t)e * H * H;
    const int*    ptok = d_perm_token + e * T;

    extern __shared__ char dsm[];
    char* sb = dsm + ((256 - (((uintptr_t)dsm) & 255)) & 255);
    const uint32_t sbase = smem_u32(sb);

    const int tid  = threadIdx.x;
    const int lane = tid & 31;
    const int wid  = tid >> 5;
    const int wm   = wid >> 1;
    const int wn   = wid & 1;

    const int a_row0 = tid >> 3;               // 0..15
    const int a_c    = tid & 7;
    const uint32_t a_dst0 = a_row0 * 128 + ((a_c ^ (a_row0 & 7)) << 4);
    uint32_t a_off[8];
    #pragma unroll
    for (int j = 0; j < 8; ++j) {
        const int gm = mBase + a_row0 + 16 * j;
        const int tok = ptok[(gm < cnt) ? gm : (cnt - 1)];
        a_off[j] = (uint32_t)(tok * H + a_c * 8);
    }
    const int b_k0 = tid >> 4;                 // 0..7
    const int b_ch = tid & 15;
    const uint32_t b_dst0 = ASTG + b_k0 * 256 + ((b_ch ^ (b_k0 & 7)) << 4);
    const __half* b_src0 = Wp + (size_t)b_k0 * H + nBase + b_ch * 8;

    const int h = lane >> 4;
    const uint32_t as0 = (uint32_t)(h ^ (lane & 7));
    const uint32_t arowbase0 = sbase + (wm * 64 + (lane & 15)) * 128;
    uint32_t boff0[4];
    {
        const int k = lane & 15;
        #pragma unroll
        for (int p = 0; p < 4; ++p) {
            const int ch = wn * 8 + p * 2 + h;
            boff0[p] = sbase + ASTG + k * 256 + ((ch ^ (k & 7)) << 4);
        }
    }

    #pragma unroll
    for (int s = 0; s < STAGES - 1; ++s) {
        const uint32_t so = sbase + s * STGB;
        #pragma unroll
        for (int j = 0; j < 8; ++j) {
            cpa16(so + a_dst0 + j * 2048, d_x16 + a_off[j] + s * BK);
            cpa16(so + b_dst0 + j * 2048, b_src0 + (size_t)(8 * j + s * BK) * H);
        }
        CP_COMMIT();
    }

    float c[4][8][4];
    #pragma unroll
    for (int mt = 0; mt < 4; ++mt)
        #pragma unroll
        for (int nt = 0; nt < 8; ++nt)
            #pragma unroll
            for (int q = 0; q < 4; ++q) c[mt][nt][q] = 0.f;

    int stage = 0, pstage = STAGES - 1;
    for (int kt = 0; kt < NCHUNK; ++kt) {
        CP_WAIT1();
        __syncthreads();

        const int nc = kt + STAGES - 1;
        if (nc < NCHUNK) {
            const uint32_t so = sbase + pstage * STGB;
            #pragma unroll
            for (int j = 0; j < 8; ++j) {
                cpa16(so + a_dst0 + j * 2048, d_x16 + a_off[j] + nc * BK);
                cpa16(so + b_dst0 + j * 2048, b_src0 + (size_t)(8 * j + nc * BK) * H);
            }
        }
        CP_COMMIT();

        const uint32_t bofs = stage * STGB;
        #pragma unroll
        for (int g = 0; g < 4; ++g) {
            uint32_t afr[4][4];
            const uint32_t aslot = (((g << 1) ^ as0) << 4);
            #pragma unroll
            for (int mt = 0; mt < 4; ++mt)
                ldsm4(arowbase0 + mt * 2048 + bofs + aslot, afr[mt]);
            #pragma unroll
            for (int pp = 0; pp < 2; ++pp) {
                uint32_t bfr[2][4];
                ldsm4t(boff0[pp * 2 + 0] + bofs + g * 4096, bfr[0]);
                ldsm4t(boff0[pp * 2 + 1] + bofs + g * 4096, bfr[1]);
                #pragma unroll
                for (int q = 0; q < 2; ++q) {
                    const int p = pp * 2 + q;
                    #pragma unroll
                    for (int mt = 0; mt < 4; ++mt) {
                        mma16816(c[mt][p * 2 + 0], afr[mt], bfr[q][0], bfr[q][1]);
                        mma16816(c[mt][p * 2 + 1], afr[mt], bfr[q][2], bfr[q][3]);
                    }
                }
            }
        }

        if (++stage == STAGES)  stage = 0;
        if (++pstage == STAGES) pstage = 0;
    }

    #pragma unroll
    for (int mt = 0; mt < 4; ++mt) {
        #pragma unroll
        for (int half = 0; half < 2; ++half) {
            const int r  = wm * 64 + mt * 16 + (lane >> 2) + half * 8;
            const int gm = mBase + r;
            if (gm < cnt) {
                const int   dest = d_perm_dest[e * T + gm];
                const float coef = d_perm_coef[e * T + gm];
                __half* orow = d_scratch16 + (size_t)dest * H + nBase;
                #pragma unroll
                for (int nt = 0; nt < 8; ++nt) {
                    const int col = wn * 64 + nt * 8 + (lane & 3) * 2;
                    *(uint32_t*)(orow + col) =
                        pk(c[mt][nt][half * 2 + 0] * coef,
                           c[mt][nt][half * 2 + 1] * coef);
                }
            }
        }
    }
}

// ============================================================
// Reduce (R12-exact: 8 elems/thread, 4096 blocks — measured 20.5us @ 68.6% DRAM)
__global__ void __launch_bounds__(256) reduce_kernel(float* __restrict__ out)
{
    const int gid = blockIdx.x * blockDim.x + threadIdx.x;
    const int t   = gid >> 7;
    const int c8  = gid & 127;
    const __half* base = d_scratch16 + (size_t)t * TOPK * H + c8 * 8;

    float acc[8];
    #pragma unroll
    for (int j = 0; j < 8; ++j) acc[j] = 0.f;
    #pragma unroll
    for (int k = 0; k < TOPK; ++k) {
        const uint4 v = *(const uint4*)(base + (size_t)k * H);
        const uint32_t w[4] = {v.x, v.y, v.z, v.w};
        #pragma unroll
        for (int j = 0; j < 4; ++j) {
            const float2 f = __half22float2(*(const __half2*)&w[j]);
            acc[j * 2 + 0] += f.x;
            acc[j * 2 + 1] += f.y;
        }
    }
    const float bi = d_bias[t];
    float* op = out + (size_t)t * H + c8 * 8;
    float4 o0, o1;
    o0.x = acc[0] + bi; o0.y = acc[1] + bi; o0.z = acc[2] + bi; o0.w = acc[3] + bi;
    o1.x = acc[4] + bi; o1.y = acc[5] + bi; o1.z = acc[6] + bi; o1.w = acc[7] + bi;
    *(float4*)(op)     = o0;
    *(float4*)(op + 4) = o1;
}

// ============================================================
extern "C" void kernel_launch(void* const* d_in, const int* in_sizes, int n_in,
                              void* d_out, int out_size)
{
    const float* tokens = (const float*)d_in[0];
    const float* rw     = (const float*)d_in[1];
    const float* rb     = (const float*)d_in[2];
    const float* ew     = (const float*)d_in[3];
    float* out = (float*)d_out;

    cudaFuncSetAttribute(moe_gemm_kernel,
                         cudaFuncAttributeMaxDynamicSharedMemorySize, DSMEM);
    cudaFuncSetAttribute(router_kernel,
                         cudaFuncAttributeMaxDynamicSharedMemorySize, LDSMEM);

    cvt_all_kernel<<<WB + XB, 256>>>(ew, tokens);
    router_kernel<<<T / 128, 256, LDSMEM>>>(rw, rb);
    dim3 g(H / BN, T / BM, E);
    moe_gemm_kernel<<<g, 128, DSMEM>>>();
    reduce_kernel<<<(T * H / 8) / 256, 256>>>(out);
}